// round 1
// baseline (speedup 1.0000x reference)
#include <cuda_runtime.h>

#define GRID 148
#define TPB  512

__constant__ float cW1[30];   // W1[q][k] = cW1[q*10+k]
__constant__ float cb1[3];
__constant__ float cgam[3];
__constant__ float cbet[3];
__constant__ float cm[6];     // m[q][j] = cm[q*2+j]
__constant__ float cth[6];    // theta[q][j]
__constant__ float cg2[8];
__constant__ float cbt2[8];
__constant__ float cW2[80];   // W2[i][c] = cW2[i*8+c]
__constant__ float cb2[10];

__device__ unsigned g_counter = 0;          // monotone ticket counter (replay-safe)
__device__ float g_partials[GRID * 16];     // [block][8 sums, 8 sumsq]

__device__ __forceinline__ float ex2f(float x) {
    float y; asm("ex2.approx.ftz.f32 %0, %1;" : "=f"(y) : "f"(x)); return y;
}
__device__ __forceinline__ float sin_fast(float x) {
    float y; asm("sin.approx.ftz.f32 %0, %1;" : "=f"(y) : "f"(x)); return y;
}

__global__ __launch_bounds__(TPB, 1)
void qfnn_kernel(const float* __restrict__ xg, float* __restrict__ outg,
                 int n, int rpb)
{
    extern __shared__ float sm[];
    float* ps  = sm;                 // 6*rpb   : cached memberships (P0_0,P0_1,t1_0,t1_1,t2_0,t2_1)
    float* xs  = sm + 6 * rpb;       // TPB*10  : x staging / output staging
    float* red = xs + TPB * 10;      // 256     : reduction scratch
    float* s2s = red + 256;          // 8
    float* t2s = s2s + 8;            // 8

    const int bid = blockIdx.x, tid = threadIdx.x;
    const int row0  = bid * rpb;
    int nrows = n - row0;
    if (nrows > rpb) nrows = rpb;
    if (nrows < 0) nrows = 0;

    // fold -log2(e)/(2*theta^2) so fuzzy = ex2(a*a*c2)
    float c2[6];
#pragma unroll
    for (int k = 0; k < 6; k++) {
        float th = cth[k];
        c2[k] = -1.4426950408889634f / (2.0f * th * th);
    }

    float accS[8], accQ[8];
#pragma unroll
    for (int c = 0; c < 8; c++) { accS[c] = 0.f; accQ[c] = 0.f; }

    const float C2 = 0.99999f * 0.99999f;
    const int ntiles = (nrows + TPB - 1) / TPB;

    // ---------------- Pass 1: x -> memberships (cached in smem) + channel sums ----------------
    for (int t = 0; t < ntiles; t++) {
        const int base = t * TPB;
        int cnt = nrows - base; if (cnt > TPB) cnt = TPB;
        __syncthreads();
        {
            const float* src = xg + (size_t)(row0 + base) * 10;
            const int tot = cnt * 10;
            for (int i = tid; i < tot; i += TPB) xs[i] = src[i];
        }
        __syncthreads();
        if (tid < cnt) {
            const int r = base + tid;
            float xv[10];
#pragma unroll
            for (int k = 0; k < 10; k++) xv[k] = xs[tid * 10 + k];

            float h[3];
#pragma unroll
            for (int q = 0; q < 3; q++) {
                float a = cb1[q];
#pragma unroll
                for (int k = 0; k < 10; k++) a = fmaf(xv[k], cW1[q * 10 + k], a);
                h[q] = a;
            }
            const float mu = (h[0] + h[1] + h[2]) * (1.0f / 3.0f);
            const float d0 = h[0] - mu, d1 = h[1] - mu, d2 = h[2] - mu;
            const float var = (d0 * d0 + d1 * d1 + d2 * d2) * (1.0f / 3.0f);
            const float rn = rsqrtf(var + 1e-5f);
            float hn[3];
            hn[0] = fmaf(d0 * rn, cgam[0], cbet[0]);
            hn[1] = fmaf(d1 * rn, cgam[1], cbet[1]);
            hn[2] = fmaf(d2 * rn, cgam[2], cbet[2]);

            float p[6];
#pragma unroll
            for (int q = 0; q < 3; q++)
#pragma unroll
                for (int j = 0; j < 2; j++) {
                    const int k = q * 2 + j;
                    const float a = hn[q] - cm[k];
                    const float f = ex2f(a * a * c2[k]);
                    const float pv = fminf(f + 1e-16f, C2);
                    p[k] = (q == 0) ? pv : (1.0f - pv);
                }
            ps[0 * rpb + r] = p[0]; ps[1 * rpb + r] = p[1];
            ps[2 * rpb + r] = p[2]; ps[3 * rpb + r] = p[3];
            ps[4 * rpb + r] = p[4]; ps[5 * rpb + r] = p[5];

            const float w00 = p[2] * p[4], w01 = p[2] * p[5];
            const float w10 = p[3] * p[4], w11 = p[3] * p[5];
            float o[8];
            o[0] = p[0] * w00; o[1] = p[0] * w01; o[2] = p[0] * w10; o[3] = p[0] * w11;
            o[4] = p[1] * w00; o[5] = p[1] * w01; o[6] = p[1] * w10; o[7] = p[1] * w11;
#pragma unroll
            for (int c = 0; c < 8; c++) {
                accS[c] += o[c];
                accQ[c] = fmaf(o[c], o[c], accQ[c]);
            }
        }
    }

    // ---------------- Block reduction (deterministic) ----------------
    {
        const int lane = tid & 31, wrp = tid >> 5;
#pragma unroll
        for (int k = 0; k < 16; k++) {
            float v = (k < 8) ? accS[k] : accQ[k - 8];
#pragma unroll
            for (int off = 16; off; off >>= 1)
                v += __shfl_down_sync(0xffffffffu, v, off);
            if (lane == 0) red[wrp * 16 + k] = v;
        }
    }
    __syncthreads();
    if (tid < 16) {
        float s = 0.f;
#pragma unroll
        for (int w = 0; w < TPB / 32; w++) s += red[w * 16 + tid];
        g_partials[bid * 16 + tid] = s;
        __threadfence();
    }
    __syncthreads();

    // ---------------- Grid barrier (ticketed, replay-safe) ----------------
    if (tid == 0) {
        __threadfence();
        const unsigned tk = atomicAdd(&g_counter, 1u);
        const unsigned target = (tk / GRID + 1u) * GRID;
        while (*((volatile unsigned*)&g_counter) < target) { }
    }
    __syncthreads();
    __threadfence();

    // ---------------- Finalize BN constants ----------------
    if (tid < 16) {
        float s0 = 0.f, s1 = 0.f, s2v = 0.f, s3 = 0.f;
#pragma unroll 4
        for (int b = 0; b < GRID; b += 4) {
            s0  += __ldcg(&g_partials[(b + 0) * 16 + tid]);
            s1  += __ldcg(&g_partials[(b + 1) * 16 + tid]);
            s2v += __ldcg(&g_partials[(b + 2) * 16 + tid]);
            s3  += __ldcg(&g_partials[(b + 3) * 16 + tid]);
        }
        red[tid] = (s0 + s1) + (s2v + s3);
    }
    __syncthreads();
    if (tid < 8) {
        const float invB = 1.0f / (float)n;
        const float muv = red[tid] * invB;
        const float msq = red[tid + 8] * invB;
        const float var = msq - muv * muv;
        const float sc = cg2[tid] * rsqrtf(var + 1e-5f);
        s2s[tid] = sc;
        t2s[tid] = cbt2[tid] - muv * sc;
    }
    __syncthreads();
    float s2r[8], t2r[8];
#pragma unroll
    for (int c = 0; c < 8; c++) { s2r[c] = s2s[c]; t2r[c] = t2s[c]; }

    // ---------------- Pass 2: memberships -> BN -> logits -> result ----------------
    for (int t = 0; t < ntiles; t++) {
        const int base = t * TPB;
        int cnt = nrows - base; if (cnt > TPB) cnt = TPB;
        __syncthreads();
        if (tid < cnt) {
            const int r = base + tid;
            const float p0 = ps[0 * rpb + r], p1 = ps[1 * rpb + r];
            const float p2 = ps[2 * rpb + r], p3 = ps[3 * rpb + r];
            const float p4 = ps[4 * rpb + r], p5 = ps[5 * rpb + r];
            const float w00 = p2 * p4, w01 = p2 * p5, w10 = p3 * p4, w11 = p3 * p5;
            float o[8];
            o[0] = p0 * w00; o[1] = p0 * w01; o[2] = p0 * w10; o[3] = p0 * w11;
            o[4] = p1 * w00; o[5] = p1 * w01; o[6] = p1 * w10; o[7] = p1 * w11;
            float y[8];
#pragma unroll
            for (int c = 0; c < 8; c++) y[c] = fmaf(o[c], s2r[c], t2r[c]);
            float lg[3];
#pragma unroll
            for (int i = 0; i < 3; i++) {
                float a = cb2[i];
#pragma unroll
                for (int c = 0; c < 8; c++) a = fmaf(y[c], cW2[i * 8 + c], a);
                lg[i] = a;
            }
            const float sg0 = sin_fast(lg[0] * 0.5f);
            const float sg1 = sin_fast(lg[1] * 0.5f);
            const float sg2 = sin_fast(lg[2] * 0.5f);
            const float pq0 = sg0 * sg0, pq1 = sg1 * sg1, pq2 = sg2 * sg2;
            const float cq0 = 1.f - pq0, cq1 = 1.f - pq1, cq2 = 1.f - pq2;
            const float tt = cq1 * cq2;
            xs[tid * 3 + 0] = cq0 * tt;
            xs[tid * 3 + 1] = pq0 * tt;
            xs[tid * 3 + 2] = cq0 * (pq1 * cq2);
        }
        __syncthreads();
        {
            float* dst = outg + (size_t)(row0 + base) * 3;
            const int tot = cnt * 3;
            for (int i = tid; i < tot; i += TPB) dst[i] = xs[i];
        }
    }
}

extern "C" void kernel_launch(void* const* d_in, const int* in_sizes, int n_in,
                              void* d_out, int out_size)
{
    const float* x = (const float*)d_in[0];
    cudaMemcpyToSymbolAsync(cW1,  d_in[1], 30 * 4, 0, cudaMemcpyDeviceToDevice, 0);
    cudaMemcpyToSymbolAsync(cb1,  d_in[2],  3 * 4, 0, cudaMemcpyDeviceToDevice, 0);
    cudaMemcpyToSymbolAsync(cgam, d_in[3],  3 * 4, 0, cudaMemcpyDeviceToDevice, 0);
    cudaMemcpyToSymbolAsync(cbet, d_in[4],  3 * 4, 0, cudaMemcpyDeviceToDevice, 0);
    cudaMemcpyToSymbolAsync(cm,   d_in[5],  6 * 4, 0, cudaMemcpyDeviceToDevice, 0);
    cudaMemcpyToSymbolAsync(cth,  d_in[6],  6 * 4, 0, cudaMemcpyDeviceToDevice, 0);
    cudaMemcpyToSymbolAsync(cg2,  d_in[7],  8 * 4, 0, cudaMemcpyDeviceToDevice, 0);
    cudaMemcpyToSymbolAsync(cbt2, d_in[8],  8 * 4, 0, cudaMemcpyDeviceToDevice, 0);
    cudaMemcpyToSymbolAsync(cW2,  d_in[9], 80 * 4, 0, cudaMemcpyDeviceToDevice, 0);
    cudaMemcpyToSymbolAsync(cb2,  d_in[10], 10 * 4, 0, cudaMemcpyDeviceToDevice, 0);

    const int n = in_sizes[0] / 10;
    const int rpb = (n + GRID - 1) / GRID;
    const size_t smem = (size_t)(6 * rpb + TPB * 10 + 256 + 16) * sizeof(float);
    cudaFuncSetAttribute(qfnn_kernel, cudaFuncAttributeMaxDynamicSharedMemorySize, (int)smem);
    qfnn_kernel<<<GRID, TPB, smem, 0>>>(x, (float*)d_out, n, rpb);
}

// round 2
// speedup vs baseline: 1.4461x; 1.4461x over previous
#include <cuda_runtime.h>

#define GRID 148
#define TPB  1024

__constant__ float cW1[30];   // W1[q][k] = cW1[q*10+k]
__constant__ float cb1[3];
__constant__ float cgam[3];
__constant__ float cbet[3];
__constant__ float cm[6];     // m[q][j] = cm[q*2+j]
__constant__ float cth[6];    // theta[q][j]
__constant__ float cg2[8];
__constant__ float cbt2[8];
__constant__ float cW2[80];   // W2[i][c] = cW2[i*8+c]
__constant__ float cb2[10];

__device__ unsigned g_counter = 0;          // monotone ticket counter (replay-safe)
__device__ float g_partials[GRID * 16];     // [block][8 sums, 8 sumsq]

__device__ __forceinline__ float ex2f(float x) {
    float y; asm("ex2.approx.ftz.f32 %0, %1;" : "=f"(y) : "f"(x)); return y;
}
__device__ __forceinline__ float sin_fast(float x) {
    float y; asm("sin.approx.ftz.f32 %0, %1;" : "=f"(y) : "f"(x)); return y;
}

__global__ __launch_bounds__(TPB, 1)
void qfnn_kernel(const float* __restrict__ xg, float* __restrict__ outg,
                 int n, int rpb)
{
    extern __shared__ float sm[];
    float* ps  = sm;                 // 6*rpb : cached memberships
    float* red = sm + 6 * rpb;       // (TPB/32)*16 reduction scratch
    float* s2s = red + (TPB / 32) * 16;  // 8
    float* t2s = s2s + 8;                // 8

    const int bid = blockIdx.x, tid = threadIdx.x;
    const int row0 = bid * rpb;
    int nrows = n - row0;
    if (nrows > rpb) nrows = rpb;
    if (nrows < 0) nrows = 0;

    // fold -log2(e)/(2*theta^2) so fuzzy = ex2(a*a*c2)
    float c2[6];
#pragma unroll
    for (int k = 0; k < 6; k++) {
        const float th = cth[k];
        c2[k] = -1.4426950408889634f / (2.0f * th * th);
    }

    float accS[8], accQ[8];
#pragma unroll
    for (int c = 0; c < 8; c++) { accS[c] = 0.f; accQ[c] = 0.f; }

    const float C2 = 0.99999f * 0.99999f;
    const int ntiles = (nrows + TPB - 1) / TPB;

    // ---------------- Pass 1 (barrier-free): x -> memberships + channel sums ----------------
    for (int t = 0; t < ntiles; t++) {
        const int r = t * TPB + tid;
        if (r < nrows) {
            const float2* xp = (const float2*)(xg + (size_t)(row0 + r) * 10);
            float2 v0 = xp[0], v1 = xp[1], v2 = xp[2], v3 = xp[3], v4 = xp[4];
            float xv[10] = {v0.x, v0.y, v1.x, v1.y, v2.x, v2.y, v3.x, v3.y, v4.x, v4.y};

            float h[3];
#pragma unroll
            for (int q = 0; q < 3; q++) {
                float a = cb1[q];
#pragma unroll
                for (int k = 0; k < 10; k++) a = fmaf(xv[k], cW1[q * 10 + k], a);
                h[q] = a;
            }
            const float mu = (h[0] + h[1] + h[2]) * (1.0f / 3.0f);
            const float d0 = h[0] - mu, d1 = h[1] - mu, d2 = h[2] - mu;
            const float var = (d0 * d0 + d1 * d1 + d2 * d2) * (1.0f / 3.0f);
            const float rn = rsqrtf(var + 1e-5f);
            float hn[3];
            hn[0] = fmaf(d0 * rn, cgam[0], cbet[0]);
            hn[1] = fmaf(d1 * rn, cgam[1], cbet[1]);
            hn[2] = fmaf(d2 * rn, cgam[2], cbet[2]);

            float p[6];
#pragma unroll
            for (int q = 0; q < 3; q++)
#pragma unroll
                for (int j = 0; j < 2; j++) {
                    const int k = q * 2 + j;
                    const float a = hn[q] - cm[k];
                    const float f = ex2f(a * a * c2[k]);
                    const float pv = fminf(f + 1e-16f, C2);
                    p[k] = (q == 0) ? pv : (1.0f - pv);
                }
            ps[0 * rpb + r] = p[0]; ps[1 * rpb + r] = p[1];
            ps[2 * rpb + r] = p[2]; ps[3 * rpb + r] = p[3];
            ps[4 * rpb + r] = p[4]; ps[5 * rpb + r] = p[5];

            const float w00 = p[2] * p[4], w01 = p[2] * p[5];
            const float w10 = p[3] * p[4], w11 = p[3] * p[5];
            float o[8];
            o[0] = p[0] * w00; o[1] = p[0] * w01; o[2] = p[0] * w10; o[3] = p[0] * w11;
            o[4] = p[1] * w00; o[5] = p[1] * w01; o[6] = p[1] * w10; o[7] = p[1] * w11;
#pragma unroll
            for (int c = 0; c < 8; c++) {
                accS[c] += o[c];
                accQ[c] = fmaf(o[c], o[c], accQ[c]);
            }
        }
    }

    // ---------------- Block reduction (deterministic) ----------------
    {
        const int lane = tid & 31, wrp = tid >> 5;
#pragma unroll
        for (int k = 0; k < 16; k++) {
            float v = (k < 8) ? accS[k] : accQ[k - 8];
#pragma unroll
            for (int off = 16; off; off >>= 1)
                v += __shfl_down_sync(0xffffffffu, v, off);
            if (lane == 0) red[wrp * 16 + k] = v;
        }
    }
    __syncthreads();
    if (tid < 16) {
        float s = 0.f;
#pragma unroll
        for (int w = 0; w < TPB / 32; w++) s += red[w * 16 + tid];
        g_partials[bid * 16 + tid] = s;
        __threadfence();
    }
    __syncthreads();

    // ---------------- Grid barrier (ticketed, replay-safe) ----------------
    if (tid == 0) {
        __threadfence();
        const unsigned tk = atomicAdd(&g_counter, 1u);
        const unsigned target = (tk / GRID + 1u) * GRID;
        while (*((volatile unsigned*)&g_counter) < target) { }
    }
    __syncthreads();
    __threadfence();

    // ---------------- Finalize BN constants ----------------
    if (tid < 16) {
        float s0 = 0.f, s1 = 0.f, s2v = 0.f, s3 = 0.f;
#pragma unroll 4
        for (int b = 0; b < GRID; b += 4) {
            s0  += __ldcg(&g_partials[(b + 0) * 16 + tid]);
            s1  += __ldcg(&g_partials[(b + 1) * 16 + tid]);
            s2v += __ldcg(&g_partials[(b + 2) * 16 + tid]);
            s3  += __ldcg(&g_partials[(b + 3) * 16 + tid]);
        }
        red[tid] = (s0 + s1) + (s2v + s3);
    }
    __syncthreads();
    if (tid < 8) {
        const float invB = 1.0f / (float)n;
        const float muv = red[tid] * invB;
        const float msq = red[tid + 8] * invB;
        const float var = msq - muv * muv;
        const float sc = cg2[tid] * rsqrtf(var + 1e-5f);
        s2s[tid] = sc;
        t2s[tid] = cbt2[tid] - muv * sc;
    }
    __syncthreads();
    float s2r[8], t2r[8];
#pragma unroll
    for (int c = 0; c < 8; c++) { s2r[c] = s2s[c]; t2r[c] = t2s[c]; }

    // ---------------- Pass 2 (barrier-free): memberships -> BN -> logits -> result ----------------
    for (int t = 0; t < ntiles; t++) {
        const int r = t * TPB + tid;
        if (r < nrows) {
            const float p0 = ps[0 * rpb + r], p1 = ps[1 * rpb + r];
            const float p2 = ps[2 * rpb + r], p3 = ps[3 * rpb + r];
            const float p4 = ps[4 * rpb + r], p5 = ps[5 * rpb + r];
            const float w00 = p2 * p4, w01 = p2 * p5, w10 = p3 * p4, w11 = p3 * p5;
            float o[8];
            o[0] = p0 * w00; o[1] = p0 * w01; o[2] = p0 * w10; o[3] = p0 * w11;
            o[4] = p1 * w00; o[5] = p1 * w01; o[6] = p1 * w10; o[7] = p1 * w11;
            float y[8];
#pragma unroll
            for (int c = 0; c < 8; c++) y[c] = fmaf(o[c], s2r[c], t2r[c]);
            float lg[3];
#pragma unroll
            for (int i = 0; i < 3; i++) {
                float a = cb2[i];
#pragma unroll
                for (int c = 0; c < 8; c++) a = fmaf(y[c], cW2[i * 8 + c], a);
                lg[i] = a;
            }
            const float sg0 = sin_fast(lg[0] * 0.5f);
            const float sg1 = sin_fast(lg[1] * 0.5f);
            const float sg2 = sin_fast(lg[2] * 0.5f);
            const float pq0 = sg0 * sg0, pq1 = sg1 * sg1, pq2 = sg2 * sg2;
            const float cq0 = 1.f - pq0, cq1 = 1.f - pq1, cq2 = 1.f - pq2;
            const float tt = cq1 * cq2;
            float* dst = outg + (size_t)(row0 + r) * 3;
            dst[0] = cq0 * tt;
            dst[1] = pq0 * tt;
            dst[2] = cq0 * (pq1 * cq2);
        }
    }
}

extern "C" void kernel_launch(void* const* d_in, const int* in_sizes, int n_in,
                              void* d_out, int out_size)
{
    const float* x = (const float*)d_in[0];
    cudaMemcpyToSymbolAsync(cW1,  d_in[1], 30 * 4, 0, cudaMemcpyDeviceToDevice, 0);
    cudaMemcpyToSymbolAsync(cb1,  d_in[2],  3 * 4, 0, cudaMemcpyDeviceToDevice, 0);
    cudaMemcpyToSymbolAsync(cgam, d_in[3],  3 * 4, 0, cudaMemcpyDeviceToDevice, 0);
    cudaMemcpyToSymbolAsync(cbet, d_in[4],  3 * 4, 0, cudaMemcpyDeviceToDevice, 0);
    cudaMemcpyToSymbolAsync(cm,   d_in[5],  6 * 4, 0, cudaMemcpyDeviceToDevice, 0);
    cudaMemcpyToSymbolAsync(cth,  d_in[6],  6 * 4, 0, cudaMemcpyDeviceToDevice, 0);
    cudaMemcpyToSymbolAsync(cg2,  d_in[7],  8 * 4, 0, cudaMemcpyDeviceToDevice, 0);
    cudaMemcpyToSymbolAsync(cbt2, d_in[8],  8 * 4, 0, cudaMemcpyDeviceToDevice, 0);
    cudaMemcpyToSymbolAsync(cW2,  d_in[9], 80 * 4, 0, cudaMemcpyDeviceToDevice, 0);
    cudaMemcpyToSymbolAsync(cb2,  d_in[10], 10 * 4, 0, cudaMemcpyDeviceToDevice, 0);

    const int n = in_sizes[0] / 10;
    const int rpb = (n + GRID - 1) / GRID;
    const size_t smem = (size_t)(6 * rpb + (TPB / 32) * 16 + 16) * sizeof(float);
    cudaFuncSetAttribute(qfnn_kernel, cudaFuncAttributeMaxDynamicSharedMemorySize, (int)smem);
    qfnn_kernel<<<GRID, TPB, smem, 0>>>(x, (float*)d_out, n, rpb);
}

// round 3
// speedup vs baseline: 1.7990x; 1.2440x over previous
#include <cuda_runtime.h>

#define GRID 148
#define TPB  1024

// Packed params: [0:30) W1, [30:33) b1, [33:36) gamma, [36:39) beta,
// [39:45) m, [45:51) theta, [51:59) g2, [59:67) bt2, [67:147) W2, [147:157) b2
__constant__ float cP[157];
__device__ float g_pack[157];

#define W1c(i)  cP[(i)]
#define B1c(i)  cP[30 + (i)]
#define GAMc(i) cP[33 + (i)]
#define BETc(i) cP[36 + (i)]
#define Mc(i)   cP[39 + (i)]
#define THc(i)  cP[45 + (i)]
#define G2c(i)  cP[51 + (i)]
#define BT2c(i) cP[59 + (i)]
#define W2c(i)  cP[67 + (i)]
#define B2c(i)  cP[147 + (i)]

__device__ unsigned g_counter = 0;          // monotone ticket counter (replay-safe)
__device__ float g_partials[GRID * 16];     // [block][8 sums, 8 sumsq]

__device__ __forceinline__ float ex2f(float x) {
    float y; asm("ex2.approx.ftz.f32 %0, %1;" : "=f"(y) : "f"(x)); return y;
}
__device__ __forceinline__ float sin_fast(float x) {
    float y; asm("sin.approx.ftz.f32 %0, %1;" : "=f"(y) : "f"(x)); return y;
}

__global__ void pack_kernel(const float* __restrict__ W1, const float* __restrict__ b1,
                            const float* __restrict__ gam, const float* __restrict__ bet,
                            const float* __restrict__ m, const float* __restrict__ th,
                            const float* __restrict__ g2, const float* __restrict__ bt2,
                            const float* __restrict__ W2, const float* __restrict__ b2)
{
    const int t = threadIdx.x;
    if      (t < 30)  g_pack[t] = W1[t];
    else if (t < 33)  g_pack[t] = b1[t - 30];
    else if (t < 36)  g_pack[t] = gam[t - 33];
    else if (t < 39)  g_pack[t] = bet[t - 36];
    else if (t < 45)  g_pack[t] = m[t - 39];
    else if (t < 51)  g_pack[t] = th[t - 45];
    else if (t < 59)  g_pack[t] = g2[t - 51];
    else if (t < 67)  g_pack[t] = bt2[t - 59];
    else if (t < 147) g_pack[t] = W2[t - 67];
    else if (t < 157) g_pack[t] = b2[t - 147];
}

__device__ __forceinline__ void row_pass1(const float* __restrict__ xv, int r,
                                          float* __restrict__ ps, int rpb,
                                          const float* __restrict__ c2,
                                          float* __restrict__ accS, float* __restrict__ accQ)
{
    float h[3];
#pragma unroll
    for (int q = 0; q < 3; q++) {
        float a = B1c(q);
#pragma unroll
        for (int k = 0; k < 10; k++) a = fmaf(xv[k], W1c(q * 10 + k), a);
        h[q] = a;
    }
    const float mu = (h[0] + h[1] + h[2]) * (1.0f / 3.0f);
    const float d0 = h[0] - mu, d1 = h[1] - mu, d2 = h[2] - mu;
    const float var = (d0 * d0 + d1 * d1 + d2 * d2) * (1.0f / 3.0f);
    const float rn = rsqrtf(var + 1e-5f);
    float hn[3];
    hn[0] = fmaf(d0 * rn, GAMc(0), BETc(0));
    hn[1] = fmaf(d1 * rn, GAMc(1), BETc(1));
    hn[2] = fmaf(d2 * rn, GAMc(2), BETc(2));

    const float C2 = 0.99999f * 0.99999f;
    float p[6];
#pragma unroll
    for (int q = 0; q < 3; q++)
#pragma unroll
        for (int j = 0; j < 2; j++) {
            const int k = q * 2 + j;
            const float a = hn[q] - Mc(k);
            const float f = ex2f(a * a * c2[k]);
            const float pv = fminf(f + 1e-16f, C2);
            p[k] = (q == 0) ? pv : (1.0f - pv);
        }
    ps[0 * rpb + r] = p[0]; ps[1 * rpb + r] = p[1];
    ps[2 * rpb + r] = p[2]; ps[3 * rpb + r] = p[3];
    ps[4 * rpb + r] = p[4]; ps[5 * rpb + r] = p[5];

    const float w00 = p[2] * p[4], w01 = p[2] * p[5];
    const float w10 = p[3] * p[4], w11 = p[3] * p[5];
    float o[8];
    o[0] = p[0] * w00; o[1] = p[0] * w01; o[2] = p[0] * w10; o[3] = p[0] * w11;
    o[4] = p[1] * w00; o[5] = p[1] * w01; o[6] = p[1] * w10; o[7] = p[1] * w11;
#pragma unroll
    for (int c = 0; c < 8; c++) {
        accS[c] += o[c];
        accQ[c] = fmaf(o[c], o[c], accQ[c]);
    }
}

__device__ __forceinline__ void row_pass2(int r, const float* __restrict__ ps, int rpb,
                                          const float* __restrict__ s2r,
                                          const float* __restrict__ t2r,
                                          float* __restrict__ dst)
{
    const float p0 = ps[0 * rpb + r], p1 = ps[1 * rpb + r];
    const float p2 = ps[2 * rpb + r], p3 = ps[3 * rpb + r];
    const float p4 = ps[4 * rpb + r], p5 = ps[5 * rpb + r];
    const float w00 = p2 * p4, w01 = p2 * p5, w10 = p3 * p4, w11 = p3 * p5;
    float o[8];
    o[0] = p0 * w00; o[1] = p0 * w01; o[2] = p0 * w10; o[3] = p0 * w11;
    o[4] = p1 * w00; o[5] = p1 * w01; o[6] = p1 * w10; o[7] = p1 * w11;
    float y[8];
#pragma unroll
    for (int c = 0; c < 8; c++) y[c] = fmaf(o[c], s2r[c], t2r[c]);
    float lg[3];
#pragma unroll
    for (int i = 0; i < 3; i++) {
        float a = B2c(i);
#pragma unroll
        for (int c = 0; c < 8; c++) a = fmaf(y[c], W2c(i * 8 + c), a);
        lg[i] = a;
    }
    const float sg0 = sin_fast(lg[0] * 0.5f);
    const float sg1 = sin_fast(lg[1] * 0.5f);
    const float sg2 = sin_fast(lg[2] * 0.5f);
    const float pq0 = sg0 * sg0, pq1 = sg1 * sg1, pq2 = sg2 * sg2;
    const float cq0 = 1.f - pq0, cq1 = 1.f - pq1, cq2 = 1.f - pq2;
    const float tt = cq1 * cq2;
    dst[0] = cq0 * tt;
    dst[1] = pq0 * tt;
    dst[2] = cq0 * (pq1 * cq2);
}

__global__ __launch_bounds__(TPB, 1)
void qfnn_kernel(const float* __restrict__ xg, float* __restrict__ outg,
                 int n, int rpb)
{
    extern __shared__ float sm[];
    float* ps  = sm;                        // 6*rpb : cached memberships
    float* red = sm + 6 * rpb;              // (TPB/32)*16 reduction scratch
    float* s2s = red + (TPB / 32) * 16;     // 8
    float* t2s = s2s + 8;                   // 8

    const int bid = blockIdx.x, tid = threadIdx.x;
    const int row0 = bid * rpb;
    int nrows = n - row0;
    if (nrows > rpb) nrows = rpb;
    if (nrows < 0) nrows = 0;

    // fold -log2(e)/(2*theta^2) so fuzzy = ex2(a*a*c2)
    float c2[6];
#pragma unroll
    for (int k = 0; k < 6; k++) {
        const float th = THc(k);
        c2[k] = -1.4426950408889634f / (2.0f * th * th);
    }

    float accS[8], accQ[8];
#pragma unroll
    for (int c = 0; c < 8; c++) { accS[c] = 0.f; accQ[c] = 0.f; }

    const int ntiles2 = (nrows + 2 * TPB - 1) / (2 * TPB);

    // ---------------- Pass 1 (barrier-free, 2-row ILP) ----------------
    for (int t = 0; t < ntiles2; t++) {
        const int r0 = t * 2 * TPB + tid;
        const int r1 = r0 + TPB;
        const bool va = r0 < nrows, vb = r1 < nrows;
        float xa[10], xb[10];
        if (va) {
            const float2* xp = (const float2*)(xg + (size_t)(row0 + r0) * 10);
            float2 v0 = xp[0], v1 = xp[1], v2 = xp[2], v3 = xp[3], v4 = xp[4];
            xa[0]=v0.x; xa[1]=v0.y; xa[2]=v1.x; xa[3]=v1.y; xa[4]=v2.x;
            xa[5]=v2.y; xa[6]=v3.x; xa[7]=v3.y; xa[8]=v4.x; xa[9]=v4.y;
        }
        if (vb) {
            const float2* xp = (const float2*)(xg + (size_t)(row0 + r1) * 10);
            float2 v0 = xp[0], v1 = xp[1], v2 = xp[2], v3 = xp[3], v4 = xp[4];
            xb[0]=v0.x; xb[1]=v0.y; xb[2]=v1.x; xb[3]=v1.y; xb[4]=v2.x;
            xb[5]=v2.y; xb[6]=v3.x; xb[7]=v3.y; xb[8]=v4.x; xb[9]=v4.y;
        }
        if (va) row_pass1(xa, r0, ps, rpb, c2, accS, accQ);
        if (vb) row_pass1(xb, r1, ps, rpb, c2, accS, accQ);
    }

    // ---------------- Block reduction (deterministic) ----------------
    {
        const int lane = tid & 31, wrp = tid >> 5;
#pragma unroll
        for (int k = 0; k < 16; k++) {
            float v = (k < 8) ? accS[k] : accQ[k - 8];
#pragma unroll
            for (int off = 16; off; off >>= 1)
                v += __shfl_down_sync(0xffffffffu, v, off);
            if (lane == 0) red[wrp * 16 + k] = v;
        }
    }
    __syncthreads();
    if (tid < 16) {
        float s = 0.f;
#pragma unroll
        for (int w = 0; w < TPB / 32; w++) s += red[w * 16 + tid];
        g_partials[bid * 16 + tid] = s;
        __threadfence();
    }
    __syncthreads();

    // ---------------- Grid barrier (ticketed, replay-safe) ----------------
    if (tid == 0) {
        __threadfence();
        const unsigned tk = atomicAdd(&g_counter, 1u);
        const unsigned target = (tk / GRID + 1u) * GRID;
        while (*((volatile unsigned*)&g_counter) < target) { }
    }
    __syncthreads();
    __threadfence();

    // ---------------- Finalize BN constants ----------------
    if (tid < 16) {
        float s0 = 0.f, s1 = 0.f, s2v = 0.f, s3 = 0.f;
#pragma unroll 4
        for (int b = 0; b < GRID; b += 4) {
            s0  += __ldcg(&g_partials[(b + 0) * 16 + tid]);
            s1  += __ldcg(&g_partials[(b + 1) * 16 + tid]);
            s2v += __ldcg(&g_partials[(b + 2) * 16 + tid]);
            s3  += __ldcg(&g_partials[(b + 3) * 16 + tid]);
        }
        red[tid] = (s0 + s1) + (s2v + s3);
    }
    __syncthreads();
    if (tid < 8) {
        const float invB = 1.0f / (float)n;
        const float muv = red[tid] * invB;
        const float msq = red[tid + 8] * invB;
        const float var = msq - muv * muv;
        const float sc = G2c(tid) * rsqrtf(var + 1e-5f);
        s2s[tid] = sc;
        t2s[tid] = BT2c(tid) - muv * sc;
    }
    __syncthreads();
    float s2r[8], t2r[8];
#pragma unroll
    for (int c = 0; c < 8; c++) { s2r[c] = s2s[c]; t2r[c] = t2s[c]; }

    // ---------------- Pass 2 (barrier-free, 2-row ILP) ----------------
    for (int t = 0; t < ntiles2; t++) {
        const int r0 = t * 2 * TPB + tid;
        const int r1 = r0 + TPB;
        float outA[3], outB[3];
        const bool va = r0 < nrows, vb = r1 < nrows;
        if (va) row_pass2(r0, ps, rpb, s2r, t2r, outA);
        if (vb) row_pass2(r1, ps, rpb, s2r, t2r, outB);
        if (va) {
            float* dst = outg + (size_t)(row0 + r0) * 3;
            dst[0] = outA[0]; dst[1] = outA[1]; dst[2] = outA[2];
        }
        if (vb) {
            float* dst = outg + (size_t)(row0 + r1) * 3;
            dst[0] = outB[0]; dst[1] = outB[1]; dst[2] = outB[2];
        }
    }
}

extern "C" void kernel_launch(void* const* d_in, const int* in_sizes, int n_in,
                              void* d_out, int out_size)
{
    const float* x = (const float*)d_in[0];

    pack_kernel<<<1, 157, 0, 0>>>(
        (const float*)d_in[1], (const float*)d_in[2], (const float*)d_in[3],
        (const float*)d_in[4], (const float*)d_in[5], (const float*)d_in[6],
        (const float*)d_in[7], (const float*)d_in[8], (const float*)d_in[9],
        (const float*)d_in[10]);

    void* packAddr = nullptr;
    cudaGetSymbolAddress(&packAddr, g_pack);
    cudaMemcpyToSymbolAsync(cP, packAddr, 157 * sizeof(float), 0,
                            cudaMemcpyDeviceToDevice, 0);

    const int n = in_sizes[0] / 10;
    const int rpb = (n + GRID - 1) / GRID;
    const size_t smem = (size_t)(6 * rpb + (TPB / 32) * 16 + 16) * sizeof(float);
    cudaFuncSetAttribute(qfnn_kernel, cudaFuncAttributeMaxDynamicSharedMemorySize, (int)smem);
    qfnn_kernel<<<GRID, TPB, smem, 0>>>(x, (float*)d_out, n, rpb);
}